// round 1
// baseline (speedup 1.0000x reference)
#include <cuda_runtime.h>
#include <cstdint>

// Problem constants
#define BB   32          // batch
#define NN   1024        // sequence
#define HH   1024        // hidden
#define NHD  16          // heads
#define DD   64          // head dim
#define BH   (BB*NHD)    // 512 flattened batch*heads
#define MROWS (BB*NN)    // 32768

// -------- scratch (device globals; no allocation allowed) --------
__device__ float g_q[BH * NN * DD];     // [512,1024,64]
__device__ float g_k[BH * NN * DD];
__device__ float g_v[BH * NN * DD];
__device__ float g_attn[BH * DD * DD];  // [512,64,64]
__device__ float g_ctx[MROWS * HH];     // [B,N,H] post-attention

// ============================================================
// GEMM NT: C[m,h] = sum_k A[m,k] * W[h,k]
// A: [M,K] row-major, W: [Ncols,K] row-major.
// MODE 0: plain row-major output C[m*Ncols+h]
// MODE 1: head-split output -> g_q layout [(b*16+nh)*1024+n][d]
// Tiles: 64x64 output, K-tile 16, 256 threads, 4x4 per thread.
// ============================================================
template<int MODE>
__global__ void gemm_nt_kernel(const float* __restrict__ A,
                               const float* __restrict__ W,
                               float* __restrict__ C,
                               int M, int Ncols, int K)
{
    __shared__ float As[16][65];   // [k][m]  padded
    __shared__ float Ws[16][65];   // [k][h]

    const int tid = threadIdx.x;
    const int bm = blockIdx.y * 64;
    const int bh = blockIdx.x * 64;
    const int tx = tid & 15;       // 0..15
    const int ty = tid >> 4;       // 0..15

    const int lr = tid >> 2;           // 0..63 row within tile
    const int lc = (tid & 3) * 4;      // 0,4,8,12

    float acc[4][4];
#pragma unroll
    for (int i = 0; i < 4; i++)
#pragma unroll
        for (int j = 0; j < 4; j++) acc[i][j] = 0.f;

    for (int k0 = 0; k0 < K; k0 += 16) {
        float4 a4 = *reinterpret_cast<const float4*>(
            &A[(size_t)(bm + lr) * K + k0 + lc]);
        As[lc + 0][lr] = a4.x; As[lc + 1][lr] = a4.y;
        As[lc + 2][lr] = a4.z; As[lc + 3][lr] = a4.w;

        float4 w4 = *reinterpret_cast<const float4*>(
            &W[(size_t)(bh + lr) * K + k0 + lc]);
        Ws[lc + 0][lr] = w4.x; Ws[lc + 1][lr] = w4.y;
        Ws[lc + 2][lr] = w4.z; Ws[lc + 3][lr] = w4.w;

        __syncthreads();

#pragma unroll
        for (int kk = 0; kk < 16; kk++) {
            float af[4], bf[4];
#pragma unroll
            for (int i = 0; i < 4; i++) af[i] = As[kk][ty * 4 + i];
#pragma unroll
            for (int j = 0; j < 4; j++) bf[j] = Ws[kk][tx * 4 + j];
#pragma unroll
            for (int i = 0; i < 4; i++)
#pragma unroll
                for (int j = 0; j < 4; j++)
                    acc[i][j] += af[i] * bf[j];
        }
        __syncthreads();
    }

#pragma unroll
    for (int i = 0; i < 4; i++) {
        const int m = bm + ty * 4 + i;
#pragma unroll
        for (int j = 0; j < 4; j++) {
            const int h = bh + tx * 4 + j;
            if (MODE == 0) {
                C[(size_t)m * Ncols + h] = acc[i][j];
            } else {
                // m = b*1024 + n ; h = nh*64 + d
                const int b  = m >> 10;
                const int n  = m & 1023;
                const int nh = h >> 6;
                const int d  = h & 63;
                C[((size_t)(b * NHD + nh) * NN + n) * DD + d] = acc[i][j];
            }
        }
    }
}

// ============================================================
// Scores: attn[b,d,e] = (1/8) * sum_n q[b,n,d]*(k[b,n,e]+pe[n,e])
// One block per b (512 blocks). Output 64x64; reduce over n in 16-row tiles.
// ============================================================
__global__ void scores_kernel(const float* __restrict__ q,
                              const float* __restrict__ k,
                              const float* __restrict__ pe,
                              float* __restrict__ attn)
{
    const int b = blockIdx.x;
    const float* qb = q + (size_t)b * NN * DD;
    const float* kb = k + (size_t)b * NN * DD;

    __shared__ float qs[16][65];
    __shared__ float ks[16][65];

    const int tid = threadIdx.x;
    const int tx = tid & 15;
    const int ty = tid >> 4;
    const int lr = tid >> 4;          // 0..15 row (n-local)
    const int lc = (tid & 15) * 4;    // 0..60 col (d/e)

    float acc[4][4];
#pragma unroll
    for (int i = 0; i < 4; i++)
#pragma unroll
        for (int j = 0; j < 4; j++) acc[i][j] = 0.f;

    for (int n0 = 0; n0 < NN; n0 += 16) {
        float4 q4 = *reinterpret_cast<const float4*>(&qb[(size_t)(n0 + lr) * DD + lc]);
        qs[lr][lc + 0] = q4.x; qs[lr][lc + 1] = q4.y;
        qs[lr][lc + 2] = q4.z; qs[lr][lc + 3] = q4.w;

        float4 k4 = *reinterpret_cast<const float4*>(&kb[(size_t)(n0 + lr) * DD + lc]);
        float4 p4 = *reinterpret_cast<const float4*>(&pe[(size_t)(n0 + lr) * DD + lc]);
        ks[lr][lc + 0] = k4.x + p4.x; ks[lr][lc + 1] = k4.y + p4.y;
        ks[lr][lc + 2] = k4.z + p4.z; ks[lr][lc + 3] = k4.w + p4.w;

        __syncthreads();

#pragma unroll
        for (int kk = 0; kk < 16; kk++) {
            float af[4], bf[4];
#pragma unroll
            for (int i = 0; i < 4; i++) af[i] = qs[kk][ty * 4 + i];
#pragma unroll
            for (int j = 0; j < 4; j++) bf[j] = ks[kk][tx * 4 + j];
#pragma unroll
            for (int i = 0; i < 4; i++)
#pragma unroll
                for (int j = 0; j < 4; j++)
                    acc[i][j] += af[i] * bf[j];
        }
        __syncthreads();
    }

    float* out = attn + (size_t)b * DD * DD;
#pragma unroll
    for (int i = 0; i < 4; i++) {
        const int d = ty * 4 + i;
#pragma unroll
        for (int j = 0; j < 4; j++) {
            const int e = tx * 4 + j;
            out[d * DD + e] = acc[i][j] * 0.125f;  // 1/sqrt(64)
        }
    }
}

// ============================================================
// Softmax over last axis (64) of attn [512*64 rows, 64].
// One warp per row; each lane holds 2 elements.
// ============================================================
__global__ void softmax64_kernel(float* __restrict__ attn)
{
    const int row  = blockIdx.x * 4 + (threadIdx.x >> 5);
    const int lane = threadIdx.x & 31;
    float* p = attn + (size_t)row * 64;

    float v0 = p[lane];
    float v1 = p[lane + 32];
    float m = fmaxf(v0, v1);
#pragma unroll
    for (int off = 16; off > 0; off >>= 1)
        m = fmaxf(m, __shfl_xor_sync(0xFFFFFFFFu, m, off));
    float e0 = __expf(v0 - m);
    float e1 = __expf(v1 - m);
    float s = e0 + e1;
#pragma unroll
    for (int off = 16; off > 0; off >>= 1)
        s += __shfl_xor_sync(0xFFFFFFFFu, s, off);
    const float inv = 1.0f / s;
    p[lane]      = e0 * inv;
    p[lane + 32] = e1 * inv;
}

// ============================================================
// AV: ctx[bb, n, nh*64+d] = sum_e attn[b,d,e] * v[b,n,e], b = bb*16+nh
// Block: (n-chunk of 16, b). 256 threads: tx=d (64), ty=n-sub (4).
// ============================================================
__global__ void av_kernel(const float* __restrict__ attn,
                          const float* __restrict__ v,
                          float* __restrict__ ctx)
{
    const int b  = blockIdx.y;
    const int n0 = blockIdx.x * 16;
    const float* ab = attn + (size_t)b * DD * DD;
    const float* vb = v + (size_t)b * NN * DD;

    __shared__ float as[64][65];
    __shared__ float vs[16][65];

    const int tid = threadIdx.x;
    for (int i = tid; i < 64 * 64; i += 256)
        as[i >> 6][i & 63] = ab[i];

    {
        const int lr = tid >> 4;          // 0..15
        const int lc = (tid & 15) * 4;
        float4 v4 = *reinterpret_cast<const float4*>(&vb[(size_t)(n0 + lr) * DD + lc]);
        vs[lr][lc + 0] = v4.x; vs[lr][lc + 1] = v4.y;
        vs[lr][lc + 2] = v4.z; vs[lr][lc + 3] = v4.w;
    }
    __syncthreads();

    const int d  = tid & 63;
    const int ny = tid >> 6;   // 0..3

    float acc[4] = {0.f, 0.f, 0.f, 0.f};
#pragma unroll
    for (int e = 0; e < 64; e++) {
        const float a = as[d][e];
#pragma unroll
        for (int i = 0; i < 4; i++)
            acc[i] += a * vs[ny + 4 * i][e];
    }

    const int bb = b >> 4;
    const int nh = b & 15;
#pragma unroll
    for (int i = 0; i < 4; i++) {
        const int n = n0 + ny + 4 * i;
        ctx[((size_t)bb * NN + n) * HH + nh * DD + d] = acc[i];
    }
}

// ============================================================
// launch
// ============================================================
extern "C" void kernel_launch(void* const* d_in, const int* in_sizes, int n_in,
                              void* d_out, int out_size)
{
    const float* query  = (const float*)d_in[0];
    const float* key    = (const float*)d_in[1];
    const float* value  = (const float*)d_in[2];
    const float* key_pe = (const float*)d_in[3];
    const float* Wq     = (const float*)d_in[4];
    const float* Wk     = (const float*)d_in[5];
    const float* Wv     = (const float*)d_in[6];
    const float* Wo     = (const float*)d_in[7];
    float* out = (float*)d_out;

    float *q, *k, *v, *attn, *ctx;
    cudaGetSymbolAddress((void**)&q,    g_q);
    cudaGetSymbolAddress((void**)&k,    g_k);
    cudaGetSymbolAddress((void**)&v,    g_v);
    cudaGetSymbolAddress((void**)&attn, g_attn);
    cudaGetSymbolAddress((void**)&ctx,  g_ctx);

    dim3 gproj(HH / 64, MROWS / 64);   // (16, 512)
    gemm_nt_kernel<1><<<gproj, 256>>>(query, Wq, q, MROWS, HH, HH);
    gemm_nt_kernel<1><<<gproj, 256>>>(key,   Wk, k, MROWS, HH, HH);
    gemm_nt_kernel<1><<<gproj, 256>>>(value, Wv, v, MROWS, HH, HH);

    scores_kernel<<<BH, 256>>>(q, k, key_pe, attn);

    softmax64_kernel<<<(BH * DD) / 4, 128>>>(attn);

    dim3 gav(NN / 16, BH);             // (64, 512)
    av_kernel<<<gav, 256>>>(attn, v, ctx);

    gemm_nt_kernel<0><<<gproj, 256>>>(ctx, Wo, out, MROWS, HH, HH);
}

// round 2
// speedup vs baseline: 5.4544x; 5.4544x over previous
#include <cuda_runtime.h>
#include <cuda_fp16.h>
#include <cstdint>

// Problem constants
#define BB   32
#define NN   1024
#define HH   1024
#define NHD  16
#define DD   64
#define BH   (BB*NHD)     // 512
#define MROWS (BB*NN)     // 32768

// -------- scratch (device globals; no allocation allowed) --------
__device__ float  g_q[BH * NN * DD];      // [512,1024,64]
__device__ float  g_k[BH * NN * DD];
__device__ float  g_v[BH * NN * DD];
__device__ float  g_attn[BH * DD * DD];   // [512,64,64]
__device__ float  g_ctx[MROWS * HH];      // [B,N,H]
__device__ __half g_xh[3][MROWS * HH];    // fp16 inputs (q,k,v sources)
__device__ __half g_ch[MROWS * HH];       // fp16 ctx
__device__ __half g_wh[4][HH * HH];       // fp16 weights (Wq,Wk,Wv,Wo)

// ============================================================
// fp32 -> fp16 convert (8 elems/thread, vectorized)
// ============================================================
struct alignas(16) H8 { __half2 a, b, c, d; };

__global__ void cvt_f32_f16(const float* __restrict__ in,
                            __half* __restrict__ out, int n)
{
    int idx = (blockIdx.x * blockDim.x + threadIdx.x) * 8;
    if (idx >= n) return;
    float4 a = *reinterpret_cast<const float4*>(in + idx);
    float4 b = *reinterpret_cast<const float4*>(in + idx + 4);
    H8 o;
    o.a = __floats2half2_rn(a.x, a.y);
    o.b = __floats2half2_rn(a.z, a.w);
    o.c = __floats2half2_rn(b.x, b.y);
    o.d = __floats2half2_rn(b.z, b.w);
    *reinterpret_cast<H8*>(out + idx) = o;
}

// ============================================================
// Tensor-core GEMM NT: C[m,h] = sum_k A[m,k] * W[h,k]   (fp16 in, fp32 out)
// A: [M,K] halfs row-major, W: [Ncols,K] halfs row-major.
// Block tile 128x128, K-tile 32, 8 warps (2m x 4n), warp tile 64x32.
// MODE 0: C[m*Ncols+h]   MODE 1: head-split scatter
// ============================================================
#define BM 128
#define BN 128
#define BKH 32           // k per tile (halfs)
#define LDSS 40          // smem row stride (halfs) => 80B rows, 16B aligned
#define NITER (HH / BKH) // 32

__device__ __forceinline__ uint32_t smem_u32(const void* p) {
    return (uint32_t)__cvta_generic_to_shared(p);
}
__device__ __forceinline__ void cp16(uint32_t dst, const void* src) {
    asm volatile("cp.async.cg.shared.global [%0], [%1], 16;\n" :: "r"(dst), "l"(src));
}
__device__ __forceinline__ void cp_commit() {
    asm volatile("cp.async.commit_group;\n");
}
template<int N> __device__ __forceinline__ void cp_wait() {
    asm volatile("cp.async.wait_group %0;\n" :: "n"(N));
}
__device__ __forceinline__ void ldsm_x4(uint32_t* r, uint32_t addr) {
    asm volatile("ldmatrix.sync.aligned.m8n8.x4.shared.b16 {%0,%1,%2,%3}, [%4];\n"
                 : "=r"(r[0]), "=r"(r[1]), "=r"(r[2]), "=r"(r[3]) : "r"(addr));
}
__device__ __forceinline__ void mma16816(float* c, const uint32_t* a, const uint32_t* b) {
    asm volatile("mma.sync.aligned.m16n8k16.row.col.f32.f16.f16.f32 "
                 "{%0,%1,%2,%3}, {%4,%5,%6,%7}, {%8,%9}, {%0,%1,%2,%3};\n"
                 : "+f"(c[0]), "+f"(c[1]), "+f"(c[2]), "+f"(c[3])
                 : "r"(a[0]), "r"(a[1]), "r"(a[2]), "r"(a[3]),
                   "r"(b[0]), "r"(b[1]));
}

template<int MODE>
__global__ void __launch_bounds__(256)
hgemm_nt(const __half* __restrict__ A, const __half* __restrict__ W,
         float* __restrict__ C, int M, int Ncols, int K)
{
    __shared__ __align__(16) __half sA[2][BM * LDSS];
    __shared__ __align__(16) __half sB[2][BN * LDSS];

    const int tid  = threadIdx.x;
    const int lane = tid & 31;
    const int wid  = tid >> 5;
    const int bm = blockIdx.y * BM;
    const int bn = blockIdx.x * BN;

    // ---- cp.async source/dest mapping: thread -> (row, 16-half chunk) ----
    const int ldrow = tid >> 1;          // 0..127
    const int ldk   = (tid & 1) * 16;    // 0 or 16 halfs
    const __half* gA = A + (size_t)(bm + ldrow) * K + ldk;
    const __half* gB = W + (size_t)(bn + ldrow) * K + ldk;
    uint32_t sAa[2], sBa[2];
    sAa[0] = smem_u32(&sA[0][ldrow * LDSS + ldk]);
    sAa[1] = smem_u32(&sA[1][ldrow * LDSS + ldk]);
    sBa[0] = smem_u32(&sB[0][ldrow * LDSS + ldk]);
    sBa[1] = smem_u32(&sB[1][ldrow * LDSS + ldk]);

    // ---- warp tiling: 2 warps over m (64 each), 4 warps over n (32 each) ----
    const int wm = (wid & 1) * 64;
    const int wn = (wid >> 1) * 32;
    const int lr = lane & 7;     // row within 8x8 tile
    const int lt = lane >> 3;    // address group 0..3

    // ldmatrix address components (halfs)
    const int arow = wm + (lt & 1) * 8 + lr;   // A: t0,t2 -> m0-7 ; t1,t3 -> m8-15
    const int akg  = lt >> 1;                  // A: k-group +0 / +1
    const int brow = wn + (lt >> 1) * 8 + lr;  // B: t0,t1 -> n0-7 ; t2,t3 -> n8-15
    const int bkg  = lt & 1;                   // B: k-group +0 / +1

    float acc[4][4][4];
#pragma unroll
    for (int i = 0; i < 4; i++)
#pragma unroll
        for (int j = 0; j < 4; j++)
#pragma unroll
            for (int r = 0; r < 4; r++) acc[i][j][r] = 0.f;

    auto issue = [&](int it, int buf) {
        const __half* ga = gA + (size_t)it * BKH;
        const __half* gb = gB + (size_t)it * BKH;
        cp16(sAa[buf],      ga);
        cp16(sAa[buf] + 16, ga + 8);
        cp16(sBa[buf],      gb);
        cp16(sBa[buf] + 16, gb + 8);
        cp_commit();
    };

    issue(0, 0);

    const uint32_t baseA[2] = { smem_u32(&sA[0][0]), smem_u32(&sA[1][0]) };
    const uint32_t baseB[2] = { smem_u32(&sB[0][0]), smem_u32(&sB[1][0]) };

    for (int it = 0; it < NITER; ++it) {
        const int cur = it & 1;
        if (it + 1 < NITER) {
            issue(it + 1, cur ^ 1);
            cp_wait<1>();
        } else {
            cp_wait<0>();
        }
        __syncthreads();

        // ---- compute on buffer cur: two k16 steps ----
#pragma unroll
        for (int s = 0; s < 2; ++s) {
            uint32_t af[4][4];
#pragma unroll
            for (int mi = 0; mi < 4; ++mi) {
                uint32_t addr = baseA[cur] +
                    (uint32_t)(((arow + mi * 16) * LDSS + (s * 2 + akg) * 8) * 2);
                ldsm_x4(af[mi], addr);
            }
            uint32_t bf[2][4];
#pragma unroll
            for (int p = 0; p < 2; ++p) {
                uint32_t addr = baseB[cur] +
                    (uint32_t)(((brow + p * 16) * LDSS + (s * 2 + bkg) * 8) * 2);
                ldsm_x4(bf[p], addr);
            }
#pragma unroll
            for (int mi = 0; mi < 4; ++mi)
#pragma unroll
                for (int ni = 0; ni < 4; ++ni)
                    mma16816(acc[mi][ni], af[mi], &bf[ni >> 1][(ni & 1) * 2]);
        }
        __syncthreads();
    }

    // ---- epilogue ----
#pragma unroll
    for (int mi = 0; mi < 4; ++mi) {
#pragma unroll
        for (int ni = 0; ni < 4; ++ni) {
            const int m0 = bm + wm + mi * 16 + (lane >> 2);
            const int n0 = bn + wn + ni * 8 + (lane & 3) * 2;
#pragma unroll
            for (int half = 0; half < 2; ++half) {
                const int m = m0 + half * 8;
                const float c0 = acc[mi][ni][half * 2 + 0];
                const float c1 = acc[mi][ni][half * 2 + 1];
                if (MODE == 0) {
                    float2* p = reinterpret_cast<float2*>(&C[(size_t)m * Ncols + n0]);
                    *p = make_float2(c0, c1);
                } else {
                    const int b  = m >> 10;
                    const int n  = m & 1023;
                    const int nh = n0 >> 6;
                    const int d  = n0 & 63;
                    float2* p = reinterpret_cast<float2*>(
                        &C[((size_t)(b * NHD + nh) * NN + n) * DD + d]);
                    *p = make_float2(c0, c1);
                }
            }
        }
    }
}

// ============================================================
// Scores: attn[b,d,e] = (1/8) * sum_n q[b,n,d]*(k[b,n,e]+pe[n,e])
// ============================================================
__global__ void scores_kernel(const float* __restrict__ q,
                              const float* __restrict__ k,
                              const float* __restrict__ pe,
                              float* __restrict__ attn)
{
    const int b = blockIdx.x;
    const float* qb = q + (size_t)b * NN * DD;
    const float* kb = k + (size_t)b * NN * DD;

    __shared__ float qs[16][65];
    __shared__ float ks[16][65];

    const int tid = threadIdx.x;
    const int tx = tid & 15;
    const int ty = tid >> 4;
    const int lr = tid >> 4;
    const int lc = (tid & 15) * 4;

    float acc[4][4];
#pragma unroll
    for (int i = 0; i < 4; i++)
#pragma unroll
        for (int j = 0; j < 4; j++) acc[i][j] = 0.f;

    for (int n0 = 0; n0 < NN; n0 += 16) {
        float4 q4 = *reinterpret_cast<const float4*>(&qb[(size_t)(n0 + lr) * DD + lc]);
        qs[lr][lc + 0] = q4.x; qs[lr][lc + 1] = q4.y;
        qs[lr][lc + 2] = q4.z; qs[lr][lc + 3] = q4.w;

        float4 k4 = *reinterpret_cast<const float4*>(&kb[(size_t)(n0 + lr) * DD + lc]);
        float4 p4 = *reinterpret_cast<const float4*>(&pe[(size_t)(n0 + lr) * DD + lc]);
        ks[lr][lc + 0] = k4.x + p4.x; ks[lr][lc + 1] = k4.y + p4.y;
        ks[lr][lc + 2] = k4.z + p4.z; ks[lr][lc + 3] = k4.w + p4.w;

        __syncthreads();

#pragma unroll
        for (int kk = 0; kk < 16; kk++) {
            float af[4], bf[4];
#pragma unroll
            for (int i = 0; i < 4; i++) af[i] = qs[kk][ty * 4 + i];
#pragma unroll
            for (int j = 0; j < 4; j++) bf[j] = ks[kk][tx * 4 + j];
#pragma unroll
            for (int i = 0; i < 4; i++)
#pragma unroll
                for (int j = 0; j < 4; j++)
                    acc[i][j] += af[i] * bf[j];
        }
        __syncthreads();
    }

    float* out = attn + (size_t)b * DD * DD;
#pragma unroll
    for (int i = 0; i < 4; i++) {
        const int d = ty * 4 + i;
#pragma unroll
        for (int j = 0; j < 4; j++) {
            const int e = tx * 4 + j;
            out[d * DD + e] = acc[i][j] * 0.125f;
        }
    }
}

// ============================================================
// Softmax over last axis (64)
// ============================================================
__global__ void softmax64_kernel(float* __restrict__ attn)
{
    const int row  = blockIdx.x * 4 + (threadIdx.x >> 5);
    const int lane = threadIdx.x & 31;
    float* p = attn + (size_t)row * 64;

    float v0 = p[lane];
    float v1 = p[lane + 32];
    float m = fmaxf(v0, v1);
#pragma unroll
    for (int off = 16; off > 0; off >>= 1)
        m = fmaxf(m, __shfl_xor_sync(0xFFFFFFFFu, m, off));
    float e0 = __expf(v0 - m);
    float e1 = __expf(v1 - m);
    float s = e0 + e1;
#pragma unroll
    for (int off = 16; off > 0; off >>= 1)
        s += __shfl_xor_sync(0xFFFFFFFFu, s, off);
    const float inv = 1.0f / s;
    p[lane]      = e0 * inv;
    p[lane + 32] = e1 * inv;
}

// ============================================================
// AV: ctx[bb, n, nh*64+d] = sum_e attn[b,d,e] * v[b,n,e]
// ============================================================
__global__ void av_kernel(const float* __restrict__ attn,
                          const float* __restrict__ v,
                          float* __restrict__ ctx)
{
    const int b  = blockIdx.y;
    const int n0 = blockIdx.x * 16;
    const float* ab = attn + (size_t)b * DD * DD;
    const float* vb = v + (size_t)b * NN * DD;

    __shared__ float as[64][65];
    __shared__ float vs[16][65];

    const int tid = threadIdx.x;
    for (int i = tid; i < 64 * 64; i += 256)
        as[i >> 6][i & 63] = ab[i];

    {
        const int lr = tid >> 4;
        const int lc = (tid & 15) * 4;
        float4 v4 = *reinterpret_cast<const float4*>(&vb[(size_t)(n0 + lr) * DD + lc]);
        vs[lr][lc + 0] = v4.x; vs[lr][lc + 1] = v4.y;
        vs[lr][lc + 2] = v4.z; vs[lr][lc + 3] = v4.w;
    }
    __syncthreads();

    const int d  = tid & 63;
    const int ny = tid >> 6;

    float acc[4] = {0.f, 0.f, 0.f, 0.f};
#pragma unroll
    for (int e = 0; e < 64; e++) {
        const float a = as[d][e];
#pragma unroll
        for (int i = 0; i < 4; i++)
            acc[i] += a * vs[ny + 4 * i][e];
    }

    const int bb = b >> 4;
    const int nh = b & 15;
#pragma unroll
    for (int i = 0; i < 4; i++) {
        const int n = n0 + ny + 4 * i;
        ctx[((size_t)bb * NN + n) * HH + nh * DD + d] = acc[i];
    }
}

// ============================================================
// launch
// ============================================================
extern "C" void kernel_launch(void* const* d_in, const int* in_sizes, int n_in,
                              void* d_out, int out_size)
{
    const float* query  = (const float*)d_in[0];
    const float* key    = (const float*)d_in[1];
    const float* value  = (const float*)d_in[2];
    const float* key_pe = (const float*)d_in[3];
    const float* Wq     = (const float*)d_in[4];
    const float* Wk     = (const float*)d_in[5];
    const float* Wv     = (const float*)d_in[6];
    const float* Wo     = (const float*)d_in[7];
    float* out = (float*)d_out;

    float *q, *k, *v, *attn, *ctx;
    __half *xh, *ch, *wh;
    cudaGetSymbolAddress((void**)&q,    g_q);
    cudaGetSymbolAddress((void**)&k,    g_k);
    cudaGetSymbolAddress((void**)&v,    g_v);
    cudaGetSymbolAddress((void**)&attn, g_attn);
    cudaGetSymbolAddress((void**)&ctx,  g_ctx);
    cudaGetSymbolAddress((void**)&xh,   g_xh);
    cudaGetSymbolAddress((void**)&ch,   g_ch);
    cudaGetSymbolAddress((void**)&wh,   g_wh);

    const int nX = MROWS * HH;        // 33,554,432
    const int nW = HH * HH;           // 1,048,576
    const int cvtThreads = 256;

    // fp32 -> fp16 converts
    cvt_f32_f16<<<nX / (8 * cvtThreads), cvtThreads>>>(query, xh + 0 * (size_t)nX, nX);
    cvt_f32_f16<<<nX / (8 * cvtThreads), cvtThreads>>>(key,   xh + 1 * (size_t)nX, nX);
    cvt_f32_f16<<<nX / (8 * cvtThreads), cvtThreads>>>(value, xh + 2 * (size_t)nX, nX);
    cvt_f32_f16<<<nW / (8 * cvtThreads), cvtThreads>>>(Wq, wh + 0 * (size_t)nW, nW);
    cvt_f32_f16<<<nW / (8 * cvtThreads), cvtThreads>>>(Wk, wh + 1 * (size_t)nW, nW);
    cvt_f32_f16<<<nW / (8 * cvtThreads), cvtThreads>>>(Wv, wh + 2 * (size_t)nW, nW);
    cvt_f32_f16<<<nW / (8 * cvtThreads), cvtThreads>>>(Wo, wh + 3 * (size_t)nW, nW);

    // projections (tensor core, head-split epilogue)
    dim3 gproj(HH / BN, MROWS / BM);   // (8, 256)
    hgemm_nt<1><<<gproj, 256>>>(xh + 0 * (size_t)nX, wh + 0 * (size_t)nW, q, MROWS, HH, HH);
    hgemm_nt<1><<<gproj, 256>>>(xh + 1 * (size_t)nX, wh + 1 * (size_t)nW, k, MROWS, HH, HH);
    hgemm_nt<1><<<gproj, 256>>>(xh + 2 * (size_t)nX, wh + 2 * (size_t)nW, v, MROWS, HH, HH);

    scores_kernel<<<BH, 256>>>(q, k, key_pe, attn);
    softmax64_kernel<<<(BH * DD) / 4, 128>>>(attn);

    dim3 gav(NN / 16, BH);
    av_kernel<<<gav, 256>>>(attn, v, ctx);

    // ctx -> fp16, then output projection
    cvt_f32_f16<<<nX / (8 * cvtThreads), cvtThreads>>>(ctx, ch, nX);
    hgemm_nt<0><<<gproj, 256>>>(ch, wh + 3 * (size_t)nW, out, MROWS, HH, HH);
}

// round 5
// speedup vs baseline: 6.0073x; 1.1014x over previous
#include <cuda_runtime.h>
#include <cuda_fp16.h>
#include <cstdint>

#define BB   32
#define NN   1024
#define HH   1024
#define NHD  16
#define DD   64
#define BH   (BB*NHD)     // 512
#define MROWS (BB*NN)     // 32768

// -------- scratch (device globals) --------
__device__ float  g_q[BH * NN * DD];
__device__ float  g_k[BH * NN * DD];
__device__ float  g_v[BH * NN * DD];
__device__ float  g_part[4][BH * DD * DD];   // scores partials
__device__ float  g_attn[BH * DD * DD];
__device__ __half g_xh[3][MROWS * HH];
__device__ __half g_wh[4][HH * HH];
__device__ __half g_ch[MROWS * HH];

// ============================================================
// fp32 -> fp16 convert
// ============================================================
struct alignas(16) H8 { __half2 a, b, c, d; };

__global__ void cvt_f32_f16(const float* __restrict__ in,
                            __half* __restrict__ out, int n)
{
    int idx = (blockIdx.x * blockDim.x + threadIdx.x) * 8;
    if (idx >= n) return;
    float4 a = *reinterpret_cast<const float4*>(in + idx);
    float4 b = *reinterpret_cast<const float4*>(in + idx + 4);
    H8 o;
    o.a = __floats2half2_rn(a.x, a.y);
    o.b = __floats2half2_rn(a.z, a.w);
    o.c = __floats2half2_rn(b.x, b.y);
    o.d = __floats2half2_rn(b.z, b.w);
    *reinterpret_cast<H8*>(out + idx) = o;
}

// ============================================================
// mma.sync helpers
// ============================================================
__device__ __forceinline__ uint32_t smem_u32(const void* p) {
    return (uint32_t)__cvta_generic_to_shared(p);
}
__device__ __forceinline__ void cp16(uint32_t dst, const void* src) {
    asm volatile("cp.async.cg.shared.global [%0], [%1], 16;\n" :: "r"(dst), "l"(src));
}
__device__ __forceinline__ void cp_commit() {
    asm volatile("cp.async.commit_group;\n");
}
template<int N> __device__ __forceinline__ void cp_wait() {
    asm volatile("cp.async.wait_group %0;\n" :: "n"(N));
}
__device__ __forceinline__ void ldsm_x4(uint32_t* r, uint32_t addr) {
    asm volatile("ldmatrix.sync.aligned.m8n8.x4.shared.b16 {%0,%1,%2,%3}, [%4];\n"
                 : "=r"(r[0]), "=r"(r[1]), "=r"(r[2]), "=r"(r[3]) : "r"(addr));
}
__device__ __forceinline__ void mma16816(float* c, const uint32_t* a, const uint32_t* b) {
    asm volatile("mma.sync.aligned.m16n8k16.row.col.f32.f16.f16.f32 "
                 "{%0,%1,%2,%3}, {%4,%5,%6,%7}, {%8,%9}, {%0,%1,%2,%3};\n"
                 : "+f"(c[0]), "+f"(c[1]), "+f"(c[2]), "+f"(c[3])
                 : "r"(a[0]), "r"(a[1]), "r"(a[2]), "r"(a[3]),
                   "r"(b[0]), "r"(b[1]));
}

// ============================================================
// HMMA GEMM NT: C[m,h] = sum_k A[m,k]*W[h,k]  (fp16 in, fp32 acc/out)
// CTA 128x256, warp tile 64x64 (8 warps: 2m x 4n), K-tile 32, 3 stages.
// MODE 0: row-major C   MODE 1: head-split scatter
// ============================================================
#define BM 128
#define BN 256
#define BKH 32
#define LDSS 40                           // halfs; 80B padded rows
#define NITER (HH / BKH)                  // 32
#define STG_A (BM * LDSS * 2)             // 10240 B
#define STG_B (BN * LDSS * 2)             // 20480 B
#define STG   (STG_A + STG_B)             // 30720 B
#define GSMEM (3 * STG + 16)

template<int MODE>
__global__ void __launch_bounds__(256, 1)
hgemm_nt(const __half* __restrict__ A, const __half* __restrict__ W,
         float* __restrict__ C)
{
    extern __shared__ __align__(16) char dynsm[];
    const uint32_t dbase = smem_u32(dynsm);

    const int tid  = threadIdx.x;
    const int lane = tid & 31;
    const int wid  = tid >> 5;
    const int bm = blockIdx.y * BM;
    const int bn = blockIdx.x * BN;

    // ---- loader mapping: thread -> (row, 16-half segment) ----
    const int arow = tid >> 1;              // 0..127
    const int akc  = (tid & 1) * 16;        // halfs: 0 or 16
    const __half* gA = A + (size_t)(bm + arow) * HH + akc;
    const uint32_t sAoff = (uint32_t)(arow * LDSS + akc) * 2;
    const __half* gB0 = W + (size_t)(bn + arow) * HH + akc;         // rows 0..127
    const __half* gB1 = W + (size_t)(bn + 128 + arow) * HH + akc;   // rows 128..255
    const uint32_t sBoff0 = (uint32_t)STG_A + (uint32_t)(arow * LDSS + akc) * 2;
    const uint32_t sBoff1 = (uint32_t)STG_A + (uint32_t)((arow + 128) * LDSS + akc) * 2;

    auto issue = [&](int it, int buf) {
        const uint32_t sb = dbase + (uint32_t)buf * STG;
        const size_t kofs = (size_t)it * BKH;
        // 16 halfs = 32 B per segment -> TWO cp16 each (R4 bug: only one)
        cp16(sb + sAoff,       gA  + kofs);
        cp16(sb + sAoff + 16,  gA  + kofs + 8);
        cp16(sb + sBoff0,      gB0 + kofs);
        cp16(sb + sBoff0 + 16, gB0 + kofs + 8);
        cp16(sb + sBoff1,      gB1 + kofs);
        cp16(sb + sBoff1 + 16, gB1 + kofs + 8);
        cp_commit();
    };

    // ---- warp tiling: 2 warps m (64), 4 warps n (64) ----
    const int wm = (wid & 1) * 64;
    const int wn = (wid >> 1) * 64;
    const int lr = lane & 7;
    const int lt = lane >> 3;
    const int arow_f = wm + (lt & 1) * 8 + lr;    // A frag row
    const int akg    = lt >> 1;
    const int brow_f = wn + (lt >> 1) * 8 + lr;   // B frag row
    const int bkg    = lt & 1;

    float acc[4][8][4];
#pragma unroll
    for (int i = 0; i < 4; i++)
#pragma unroll
        for (int j = 0; j < 8; j++)
#pragma unroll
            for (int r = 0; r < 4; r++) acc[i][j][r] = 0.f;

    issue(0, 0);
    issue(1, 1);

    for (int it = 0; it < NITER; ++it) {
        if (it + 1 < NITER) cp_wait<1>(); else cp_wait<0>();
        __syncthreads();

        if (it + 2 < NITER) issue(it + 2, (it + 2) % 3);

        const uint32_t sb = dbase + (uint32_t)(it % 3) * STG;

#pragma unroll
        for (int s = 0; s < 2; ++s) {
            uint32_t af[4][4];
#pragma unroll
            for (int mi = 0; mi < 4; ++mi)
                ldsm_x4(af[mi], sb +
                    (uint32_t)(((arow_f + mi * 16) * LDSS + (s * 2 + akg) * 8) * 2));
            uint32_t bf[4][4];
#pragma unroll
            for (int p = 0; p < 4; ++p)
                ldsm_x4(bf[p], sb + STG_A +
                    (uint32_t)(((brow_f + p * 16) * LDSS + (s * 2 + bkg) * 8) * 2));
#pragma unroll
            for (int mi = 0; mi < 4; ++mi)
#pragma unroll
                for (int ni = 0; ni < 8; ++ni)
                    mma16816(acc[mi][ni], af[mi], &bf[ni >> 1][(ni & 1) * 2]);
        }
    }

    // ---- epilogue ----
#pragma unroll
    for (int mi = 0; mi < 4; ++mi) {
#pragma unroll
        for (int ni = 0; ni < 8; ++ni) {
            const int m0 = bm + wm + mi * 16 + (lane >> 2);
            const int n0 = bn + wn + ni * 8 + (lane & 3) * 2;
#pragma unroll
            for (int h = 0; h < 2; ++h) {
                const int m = m0 + h * 8;
                const float c0 = acc[mi][ni][h * 2 + 0];
                const float c1 = acc[mi][ni][h * 2 + 1];
                if (MODE == 0) {
                    *reinterpret_cast<float2*>(&C[(size_t)m * HH + n0]) =
                        make_float2(c0, c1);
                } else {
                    const int b  = m >> 10;
                    const int n  = m & 1023;
                    const int nh = n0 >> 6;
                    const int d  = n0 & 63;
                    *reinterpret_cast<float2*>(
                        &C[((size_t)(b * NHD + nh) * NN + n) * DD + d]) =
                        make_float2(c0, c1);
                }
            }
        }
    }
}

// ============================================================
// Scores partials: part[s][b,d,e] = sum_{n in slice s} q[b,n,d]*(k[b,n,e]+pe[n,e])
// grid (4, 512); each block reduces 256 n-rows.
// ============================================================
__global__ void scores_part_kernel(const float* __restrict__ q,
                                   const float* __restrict__ k,
                                   const float* __restrict__ pe,
                                   float* __restrict__ part)
{
    const int s = blockIdx.x;
    const int b = blockIdx.y;
    const float* qb = q + (size_t)b * NN * DD;
    const float* kb = k + (size_t)b * NN * DD;
    const int nbase = s * 256;

    __shared__ float qs[16][65];
    __shared__ float ks[16][65];

    const int tid = threadIdx.x;
    const int tx = tid & 15;
    const int ty = tid >> 4;
    const int lr = tid >> 4;
    const int lc = (tid & 15) * 4;

    float acc[4][4];
#pragma unroll
    for (int i = 0; i < 4; i++)
#pragma unroll
        for (int j = 0; j < 4; j++) acc[i][j] = 0.f;

    for (int n0 = nbase; n0 < nbase + 256; n0 += 16) {
        float4 q4 = *reinterpret_cast<const float4*>(&qb[(size_t)(n0 + lr) * DD + lc]);
        qs[lr][lc + 0] = q4.x; qs[lr][lc + 1] = q4.y;
        qs[lr][lc + 2] = q4.z; qs[lr][lc + 3] = q4.w;

        float4 k4 = *reinterpret_cast<const float4*>(&kb[(size_t)(n0 + lr) * DD + lc]);
        float4 p4 = *reinterpret_cast<const float4*>(&pe[(size_t)(n0 + lr) * DD + lc]);
        ks[lr][lc + 0] = k4.x + p4.x; ks[lr][lc + 1] = k4.y + p4.y;
        ks[lr][lc + 2] = k4.z + p4.z; ks[lr][lc + 3] = k4.w + p4.w;

        __syncthreads();

#pragma unroll
        for (int kk = 0; kk < 16; kk++) {
            float af[4], bf[4];
#pragma unroll
            for (int i = 0; i < 4; i++) af[i] = qs[kk][ty * 4 + i];
#pragma unroll
            for (int j = 0; j < 4; j++) bf[j] = ks[kk][tx * 4 + j];
#pragma unroll
            for (int i = 0; i < 4; i++)
#pragma unroll
                for (int j = 0; j < 4; j++)
                    acc[i][j] += af[i] * bf[j];
        }
        __syncthreads();
    }

    float* out = part + ((size_t)s * BH + b) * DD * DD;
#pragma unroll
    for (int i = 0; i < 4; i++) {
        const int d = ty * 4 + i;
#pragma unroll
        for (int j = 0; j < 4; j++) {
            const int e = tx * 4 + j;
            out[d * DD + e] = acc[i][j];
        }
    }
}

// ============================================================
// Sum partials + scale + softmax over last axis (64)
// ============================================================
__global__ void softmax64_kernel(const float* __restrict__ part,
                                 float* __restrict__ attn)
{
    const int row  = blockIdx.x * 4 + (threadIdx.x >> 5);   // b*64+d
    const int lane = threadIdx.x & 31;
    const size_t stride = (size_t)BH * DD * DD;
    const size_t base = (size_t)row * 64;

    float v0 = 0.f, v1 = 0.f;
#pragma unroll
    for (int s = 0; s < 4; ++s) {
        v0 += part[s * stride + base + lane];
        v1 += part[s * stride + base + lane + 32];
    }
    v0 *= 0.125f; v1 *= 0.125f;

    float m = fmaxf(v0, v1);
#pragma unroll
    for (int off = 16; off > 0; off >>= 1)
        m = fmaxf(m, __shfl_xor_sync(0xFFFFFFFFu, m, off));
    float e0 = __expf(v0 - m);
    float e1 = __expf(v1 - m);
    float sum = e0 + e1;
#pragma unroll
    for (int off = 16; off > 0; off >>= 1)
        sum += __shfl_xor_sync(0xFFFFFFFFu, sum, off);
    const float inv = 1.0f / sum;
    attn[base + lane]      = e0 * inv;
    attn[base + lane + 32] = e1 * inv;
}

// ============================================================
// AV: ctx_h[bb, n, nh*64+d] = sum_e attn[b,d,e]*v[b,n,e]  (fp16 out)
// grid (16, 512): 64 n-rows per block.
// ============================================================
__global__ void av_kernel(const float* __restrict__ attn,
                          const float* __restrict__ v,
                          __half* __restrict__ ch)
{
    const int b  = blockIdx.y;
    const int n0 = blockIdx.x * 64;
    const float* ab = attn + (size_t)b * DD * DD;
    const float* vb = v + (size_t)b * NN * DD;

    __shared__ float as[64][65];
    __shared__ float vs[64][65];

    const int tid = threadIdx.x;
    for (int i = tid; i < 64 * 64; i += 256)
        as[i >> 6][i & 63] = ab[i];

    {
        const int lr = tid >> 2;            // 0..63
        const int lc = (tid & 3) * 16;      // 0,16,32,48
#pragma unroll
        for (int u = 0; u < 4; ++u) {
            float4 v4 = *reinterpret_cast<const float4*>(
                &vb[(size_t)(n0 + lr) * DD + lc + u * 4]);
            vs[lr][lc + u * 4 + 0] = v4.x; vs[lr][lc + u * 4 + 1] = v4.y;
            vs[lr][lc + u * 4 + 2] = v4.z; vs[lr][lc + u * 4 + 3] = v4.w;
        }
    }
    __syncthreads();

    const int d = tid & 63;
    const int g = tid >> 6;   // 0..3

    float acc[16];
#pragma unroll
    for (int i = 0; i < 16; i++) acc[i] = 0.f;

#pragma unroll 8
    for (int e = 0; e < 64; e++) {
        const float a = as[d][e];
#pragma unroll
        for (int i = 0; i < 16; i++)
            acc[i] += a * vs[g + 4 * i][e];
    }

    const int bb = b >> 4;
    const int nh = b & 15;
#pragma unroll
    for (int i = 0; i < 16; i++) {
        const int n = n0 + g + 4 * i;
        ch[((size_t)bb * NN + n) * HH + nh * DD + d] = __float2half_rn(acc[i]);
    }
}

// ============================================================
// launch
// ============================================================
extern "C" void kernel_launch(void* const* d_in, const int* in_sizes, int n_in,
                              void* d_out, int out_size)
{
    const float* query  = (const float*)d_in[0];
    const float* key    = (const float*)d_in[1];
    const float* value  = (const float*)d_in[2];
    const float* key_pe = (const float*)d_in[3];
    const float* Wq     = (const float*)d_in[4];
    const float* Wk     = (const float*)d_in[5];
    const float* Wv     = (const float*)d_in[6];
    const float* Wo     = (const float*)d_in[7];
    float* out = (float*)d_out;

    float *q, *k, *v, *attn, *part;
    __half *xh, *wh, *ch;
    cudaGetSymbolAddress((void**)&q,    g_q);
    cudaGetSymbolAddress((void**)&k,    g_k);
    cudaGetSymbolAddress((void**)&v,    g_v);
    cudaGetSymbolAddress((void**)&attn, g_attn);
    cudaGetSymbolAddress((void**)&part, g_part);
    cudaGetSymbolAddress((void**)&xh,   g_xh);
    cudaGetSymbolAddress((void**)&wh,   g_wh);
    cudaGetSymbolAddress((void**)&ch,   g_ch);

    static bool attr_done = false;
    if (!attr_done) {
        cudaFuncSetAttribute(hgemm_nt<0>, cudaFuncAttributeMaxDynamicSharedMemorySize, GSMEM);
        cudaFuncSetAttribute(hgemm_nt<1>, cudaFuncAttributeMaxDynamicSharedMemorySize, GSMEM);
        attr_done = true;
    }

    const int nX = MROWS * HH;
    const int nW = HH * HH;

    cvt_f32_f16<<<nX / 2048, 256>>>(query, xh + 0 * (size_t)nX, nX);
    cvt_f32_f16<<<nX / 2048, 256>>>(key,   xh + 1 * (size_t)nX, nX);
    cvt_f32_f16<<<nX / 2048, 256>>>(value, xh + 2 * (size_t)nX, nX);
    cvt_f32_f16<<<nW / 2048, 256>>>(Wq, wh + 0 * (size_t)nW, nW);
    cvt_f32_f16<<<nW / 2048, 256>>>(Wk, wh + 1 * (size_t)nW, nW);
    cvt_f32_f16<<<nW / 2048, 256>>>(Wv, wh + 2 * (size_t)nW, nW);
    cvt_f32_f16<<<nW / 2048, 256>>>(Wo, wh + 3 * (size_t)nW, nW);

    dim3 gg(HH / BN, MROWS / BM);   // (4, 256)
    hgemm_nt<1><<<gg, 256, GSMEM>>>(xh + 0 * (size_t)nX, wh + 0 * (size_t)nW, q);
    hgemm_nt<1><<<gg, 256, GSMEM>>>(xh + 1 * (size_t)nX, wh + 1 * (size_t)nW, k);
    hgemm_nt<1><<<gg, 256, GSMEM>>>(xh + 2 * (size_t)nX, wh + 2 * (size_t)nW, v);

    scores_part_kernel<<<dim3(4, BH), 256>>>(q, k, key_pe, part);
    softmax64_kernel<<<(BH * DD) / 4, 128>>>(part, attn);

    av_kernel<<<dim3(NN / 64, BH), 256>>>(attn, v, ch);

    hgemm_nt<0><<<gg, 256, GSMEM>>>(ch, wh + 3 * (size_t)nW, out);
}

// round 6
// speedup vs baseline: 6.3648x; 1.0595x over previous
#include <cuda_runtime.h>
#include <cuda_fp16.h>
#include <cstdint>

#define BB   32
#define NN   1024
#define HH   1024
#define NHD  16
#define DD   64
#define BH   (BB*NHD)     // 512
#define MROWS (BB*NN)     // 32768

// -------- scratch (device globals) --------
__device__ float  g_q[BH * NN * DD];
__device__ float  g_k[BH * NN * DD];
__device__ float  g_v[BH * NN * DD];
__device__ float  g_part[4][BH * DD * DD];   // scores partials
__device__ float  g_attn[BH * DD * DD];
__device__ __half g_xh[3][MROWS * HH];
__device__ __half g_wh[4][HH * HH];
__device__ __half g_ch[MROWS * HH];

// ============================================================
// fp32 -> fp16 convert
// ============================================================
struct alignas(16) H8 { __half2 a, b, c, d; };

__global__ void cvt_f32_f16(const float* __restrict__ in,
                            __half* __restrict__ out, int n)
{
    int idx = (blockIdx.x * blockDim.x + threadIdx.x) * 8;
    if (idx >= n) return;
    float4 a = *reinterpret_cast<const float4*>(in + idx);
    float4 b = *reinterpret_cast<const float4*>(in + idx + 4);
    H8 o;
    o.a = __floats2half2_rn(a.x, a.y);
    o.b = __floats2half2_rn(a.z, a.w);
    o.c = __floats2half2_rn(b.x, b.y);
    o.d = __floats2half2_rn(b.z, b.w);
    *reinterpret_cast<H8*>(out + idx) = o;
}

// ============================================================
// mma.sync helpers
// ============================================================
__device__ __forceinline__ uint32_t smem_u32(const void* p) {
    return (uint32_t)__cvta_generic_to_shared(p);
}
__device__ __forceinline__ void cp16(uint32_t dst, const void* src) {
    asm volatile("cp.async.cg.shared.global [%0], [%1], 16;\n" :: "r"(dst), "l"(src));
}
__device__ __forceinline__ void cp_commit() {
    asm volatile("cp.async.commit_group;\n");
}
template<int N> __device__ __forceinline__ void cp_wait() {
    asm volatile("cp.async.wait_group %0;\n" :: "n"(N));
}
__device__ __forceinline__ void ldsm_x4(uint32_t* r, uint32_t addr) {
    asm volatile("ldmatrix.sync.aligned.m8n8.x4.shared.b16 {%0,%1,%2,%3}, [%4];\n"
                 : "=r"(r[0]), "=r"(r[1]), "=r"(r[2]), "=r"(r[3]) : "r"(addr));
}
__device__ __forceinline__ void mma16816(float* c, const uint32_t* a, const uint32_t* b) {
    asm volatile("mma.sync.aligned.m16n8k16.row.col.f32.f16.f16.f32 "
                 "{%0,%1,%2,%3}, {%4,%5,%6,%7}, {%8,%9}, {%0,%1,%2,%3};\n"
                 : "+f"(c[0]), "+f"(c[1]), "+f"(c[2]), "+f"(c[3])
                 : "r"(a[0]), "r"(a[1]), "r"(a[2]), "r"(a[3]),
                   "r"(b[0]), "r"(b[1]));
}

// ============================================================
// HMMA GEMM NT: C[m,h] = sum_k A[m,k]*W[h,k]  (fp16 in, fp32 acc/out)
// CTA 128x256, 16 warps (4m x 4n), warp tile 32x64, K-tile 32, 3 stages.
// 512 threads -> 4 warps/SMSP for latency hiding.
// MODE 0: row-major C   MODE 1: head-split scatter
// ============================================================
#define BM 128
#define BN 256
#define BKH 32
#define LDSS 40                           // halfs; 80B padded rows
#define NITER (HH / BKH)                  // 32
#define STG_A (BM * LDSS * 2)             // 10240 B
#define STG_B (BN * LDSS * 2)             // 20480 B
#define STG   (STG_A + STG_B)             // 30720 B
#define GSMEM (3 * STG + 16)

template<int MODE>
__global__ void __launch_bounds__(512, 1)
hgemm_nt(const __half* __restrict__ A, const __half* __restrict__ W,
         float* __restrict__ C)
{
    extern __shared__ __align__(16) char dynsm[];
    const uint32_t dbase = smem_u32(dynsm);

    const int tid  = threadIdx.x;
    const int lane = tid & 31;
    const int wid  = tid >> 5;
    const int bm = blockIdx.y * BM;
    const int bn = blockIdx.x * BN;

    // ---- loader mapping: thread -> (row, 8-half chunk); 3 cp16/thread ----
    const int lrow = tid >> 2;             // 0..127
    const int lcol = (tid & 3) * 8;        // halfs: 0,8,16,24
    const __half* gA  = A + (size_t)(bm + lrow) * HH + lcol;
    const __half* gB0 = W + (size_t)(bn + lrow) * HH + lcol;
    const __half* gB1 = W + (size_t)(bn + 128 + lrow) * HH + lcol;
    const uint32_t sAoff  = (uint32_t)(lrow * LDSS + lcol) * 2;
    const uint32_t sBoff0 = (uint32_t)STG_A + (uint32_t)(lrow * LDSS + lcol) * 2;
    const uint32_t sBoff1 = (uint32_t)STG_A + (uint32_t)((lrow + 128) * LDSS + lcol) * 2;

    auto issue = [&](int it, int buf) {
        const uint32_t sb = dbase + (uint32_t)buf * STG;
        const size_t kofs = (size_t)it * BKH;
        cp16(sb + sAoff,  gA  + kofs);
        cp16(sb + sBoff0, gB0 + kofs);
        cp16(sb + sBoff1, gB1 + kofs);
        cp_commit();
    };

    // ---- warp tiling: 4 warps m (32 each), 4 warps n (64 each) ----
    const int wm = (wid & 3) * 32;
    const int wn = (wid >> 2) * 64;
    const int lr = lane & 7;
    const int lt = lane >> 3;
    const int arow_f = wm + (lt & 1) * 8 + lr;    // A frag row
    const int akg    = lt >> 1;
    const int brow_f = wn + (lt >> 1) * 8 + lr;   // B frag row
    const int bkg    = lt & 1;

    float acc[2][8][4];
#pragma unroll
    for (int i = 0; i < 2; i++)
#pragma unroll
        for (int j = 0; j < 8; j++)
#pragma unroll
            for (int r = 0; r < 4; r++) acc[i][j][r] = 0.f;

    issue(0, 0);
    issue(1, 1);

    for (int it = 0; it < NITER; ++it) {
        if (it + 1 < NITER) cp_wait<1>(); else cp_wait<0>();
        __syncthreads();

        if (it + 2 < NITER) issue(it + 2, (it + 2) % 3);

        const uint32_t sb = dbase + (uint32_t)(it % 3) * STG;

#pragma unroll
        for (int s = 0; s < 2; ++s) {
            uint32_t af[2][4];
#pragma unroll
            for (int mi = 0; mi < 2; ++mi)
                ldsm_x4(af[mi], sb +
                    (uint32_t)(((arow_f + mi * 16) * LDSS + (s * 2 + akg) * 8) * 2));
            uint32_t bf[4][4];
#pragma unroll
            for (int p = 0; p < 4; ++p)
                ldsm_x4(bf[p], sb + STG_A +
                    (uint32_t)(((brow_f + p * 16) * LDSS + (s * 2 + bkg) * 8) * 2));
#pragma unroll
            for (int mi = 0; mi < 2; ++mi)
#pragma unroll
                for (int ni = 0; ni < 8; ++ni)
                    mma16816(acc[mi][ni], af[mi], &bf[ni >> 1][(ni & 1) * 2]);
        }
    }

    // ---- epilogue ----
#pragma unroll
    for (int mi = 0; mi < 2; ++mi) {
#pragma unroll
        for (int ni = 0; ni < 8; ++ni) {
            const int m0 = bm + wm + mi * 16 + (lane >> 2);
            const int n0 = bn + wn + ni * 8 + (lane & 3) * 2;
#pragma unroll
            for (int h = 0; h < 2; ++h) {
                const int m = m0 + h * 8;
                const float c0 = acc[mi][ni][h * 2 + 0];
                const float c1 = acc[mi][ni][h * 2 + 1];
                if (MODE == 0) {
                    *reinterpret_cast<float2*>(&C[(size_t)m * HH + n0]) =
                        make_float2(c0, c1);
                } else {
                    const int b  = m >> 10;
                    const int n  = m & 1023;
                    const int nh = n0 >> 6;
                    const int d  = n0 & 63;
                    *reinterpret_cast<float2*>(
                        &C[((size_t)(b * NHD + nh) * NN + n) * DD + d]) =
                        make_float2(c0, c1);
                }
            }
        }
    }
}

// ============================================================
// Scores partials: part[s][b,d,e] = sum_{n in slice s} q[b,n,d]*(k[b,n,e]+pe[n,e])
// ============================================================
__global__ void scores_part_kernel(const float* __restrict__ q,
                                   const float* __restrict__ k,
                                   const float* __restrict__ pe,
                                   float* __restrict__ part)
{
    const int s = blockIdx.x;
    const int b = blockIdx.y;
    const float* qb = q + (size_t)b * NN * DD;
    const float* kb = k + (size_t)b * NN * DD;
    const int nbase = s * 256;

    __shared__ float qs[16][65];
    __shared__ float ks[16][65];

    const int tid = threadIdx.x;
    const int tx = tid & 15;
    const int ty = tid >> 4;
    const int lr = tid >> 4;
    const int lc = (tid & 15) * 4;

    float acc[4][4];
#pragma unroll
    for (int i = 0; i < 4; i++)
#pragma unroll
        for (int j = 0; j < 4; j++) acc[i][j] = 0.f;

    for (int n0 = nbase; n0 < nbase + 256; n0 += 16) {
        float4 q4 = *reinterpret_cast<const float4*>(&qb[(size_t)(n0 + lr) * DD + lc]);
        qs[lr][lc + 0] = q4.x; qs[lr][lc + 1] = q4.y;
        qs[lr][lc + 2] = q4.z; qs[lr][lc + 3] = q4.w;

        float4 k4 = *reinterpret_cast<const float4*>(&kb[(size_t)(n0 + lr) * DD + lc]);
        float4 p4 = *reinterpret_cast<const float4*>(&pe[(size_t)(n0 + lr) * DD + lc]);
        ks[lr][lc + 0] = k4.x + p4.x; ks[lr][lc + 1] = k4.y + p4.y;
        ks[lr][lc + 2] = k4.z + p4.z; ks[lr][lc + 3] = k4.w + p4.w;

        __syncthreads();

#pragma unroll
        for (int kk = 0; kk < 16; kk++) {
            float af[4], bf[4];
#pragma unroll
            for (int i = 0; i < 4; i++) af[i] = qs[kk][ty * 4 + i];
#pragma unroll
            for (int j = 0; j < 4; j++) bf[j] = ks[kk][tx * 4 + j];
#pragma unroll
            for (int i = 0; i < 4; i++)
#pragma unroll
                for (int j = 0; j < 4; j++)
                    acc[i][j] += af[i] * bf[j];
        }
        __syncthreads();
    }

    float* out = part + ((size_t)s * BH + b) * DD * DD;
#pragma unroll
    for (int i = 0; i < 4; i++) {
        const int d = ty * 4 + i;
#pragma unroll
        for (int j = 0; j < 4; j++) {
            const int e = tx * 4 + j;
            out[d * DD + e] = acc[i][j];
        }
    }
}

// ============================================================
// Sum partials + scale + softmax over last axis (64)
// ============================================================
__global__ void softmax64_kernel(const float* __restrict__ part,
                                 float* __restrict__ attn)
{
    const int row  = blockIdx.x * 4 + (threadIdx.x >> 5);   // b*64+d
    const int lane = threadIdx.x & 31;
    const size_t stride = (size_t)BH * DD * DD;
    const size_t base = (size_t)row * 64;

    float v0 = 0.f, v1 = 0.f;
#pragma unroll
    for (int s = 0; s < 4; ++s) {
        v0 += part[s * stride + base + lane];
        v1 += part[s * stride + base + lane + 32];
    }
    v0 *= 0.125f; v1 *= 0.125f;

    float m = fmaxf(v0, v1);
#pragma unroll
    for (int off = 16; off > 0; off >>= 1)
        m = fmaxf(m, __shfl_xor_sync(0xFFFFFFFFu, m, off));
    float e0 = __expf(v0 - m);
    float e1 = __expf(v1 - m);
    float sum = e0 + e1;
#pragma unroll
    for (int off = 16; off > 0; off >>= 1)
        sum += __shfl_xor_sync(0xFFFFFFFFu, sum, off);
    const float inv = 1.0f / sum;
    attn[base + lane]      = e0 * inv;
    attn[base + lane + 32] = e1 * inv;
}

// ============================================================
// AV: ctx_h[bb, n, nh*64+d] = sum_e attn[b,d,e]*v[b,n,e]  (fp16 out)
// ============================================================
__global__ void av_kernel(const float* __restrict__ attn,
                          const float* __restrict__ v,
                          __half* __restrict__ ch)
{
    const int b  = blockIdx.y;
    const int n0 = blockIdx.x * 64;
    const float* ab = attn + (size_t)b * DD * DD;
    const float* vb = v + (size_t)b * NN * DD;

    __shared__ float as[64][65];
    __shared__ float vs[64][65];

    const int tid = threadIdx.x;
    for (int i = tid; i < 64 * 64; i += 256)
        as[i >> 6][i & 63] = ab[i];

    {
        const int lr = tid >> 2;            // 0..63
        const int lc = (tid & 3) * 16;      // 0,16,32,48
#pragma unroll
        for (int u = 0; u < 4; ++u) {
            float4 v4 = *reinterpret_cast<const float4*>(
                &vb[(size_t)(n0 + lr) * DD + lc + u * 4]);
            vs[lr][lc + u * 4 + 0] = v4.x; vs[lr][lc + u * 4 + 1] = v4.y;
            vs[lr][lc + u * 4 + 2] = v4.z; vs[lr][lc + u * 4 + 3] = v4.w;
        }
    }
    __syncthreads();

    const int d = tid & 63;
    const int g = tid >> 6;   // 0..3

    float acc[16];
#pragma unroll
    for (int i = 0; i < 16; i++) acc[i] = 0.f;

#pragma unroll 8
    for (int e = 0; e < 64; e++) {
        const float a = as[d][e];
#pragma unroll
        for (int i = 0; i < 16; i++)
            acc[i] += a * vs[g + 4 * i][e];
    }

    const int bb = b >> 4;
    const int nh = b & 15;
#pragma unroll
    for (int i = 0; i < 16; i++) {
        const int n = n0 + g + 4 * i;
        ch[((size_t)bb * NN + n) * HH + nh * DD + d] = __float2half_rn(acc[i]);
    }
}

// ============================================================
// launch  (ordered so launch #6 = hgemm_nt for ncu -s 5 -c 1)
// ============================================================
extern "C" void kernel_launch(void* const* d_in, const int* in_sizes, int n_in,
                              void* d_out, int out_size)
{
    const float* query  = (const float*)d_in[0];
    const float* key    = (const float*)d_in[1];
    const float* value  = (const float*)d_in[2];
    const float* key_pe = (const float*)d_in[3];
    const float* Wq     = (const float*)d_in[4];
    const float* Wk     = (const float*)d_in[5];
    const float* Wv     = (const float*)d_in[6];
    const float* Wo     = (const float*)d_in[7];
    float* out = (float*)d_out;

    float *q, *k, *v, *attn, *part;
    __half *xh, *wh, *ch;
    cudaGetSymbolAddress((void**)&q,    g_q);
    cudaGetSymbolAddress((void**)&k,    g_k);
    cudaGetSymbolAddress((void**)&v,    g_v);
    cudaGetSymbolAddress((void**)&attn, g_attn);
    cudaGetSymbolAddress((void**)&part, g_part);
    cudaGetSymbolAddress((void**)&xh,   g_xh);
    cudaGetSymbolAddress((void**)&wh,   g_wh);
    cudaGetSymbolAddress((void**)&ch,   g_ch);

    static bool attr_done = false;
    if (!attr_done) {
        cudaFuncSetAttribute(hgemm_nt<0>, cudaFuncAttributeMaxDynamicSharedMemorySize, GSMEM);
        cudaFuncSetAttribute(hgemm_nt<1>, cudaFuncAttributeMaxDynamicSharedMemorySize, GSMEM);
        attr_done = true;
    }

    const int nX = MROWS * HH;
    const int nW = HH * HH;

    dim3 gg(HH / BN, MROWS / BM);   // (4, 256)

    // launches 1-5: converts needed for the first GEMM
    cvt_f32_f16<<<nX / 2048, 256>>>(query, xh + 0 * (size_t)nX, nX);   // 1
    cvt_f32_f16<<<nW / 2048, 256>>>(Wq, wh + 0 * (size_t)nW, nW);      // 2
    cvt_f32_f16<<<nX / 2048, 256>>>(key,   xh + 1 * (size_t)nX, nX);   // 3
    cvt_f32_f16<<<nW / 2048, 256>>>(Wk, wh + 1 * (size_t)nW, nW);      // 4
    cvt_f32_f16<<<nX / 2048, 256>>>(value, xh + 2 * (size_t)nX, nX);   // 5

    // launch 6: profiled by ncu (-s 5 -c 1)
    hgemm_nt<1><<<gg, 512, GSMEM>>>(xh + 0 * (size_t)nX, wh + 0 * (size_t)nW, q);  // 6

    cvt_f32_f16<<<nW / 2048, 256>>>(Wv, wh + 2 * (size_t)nW, nW);      // 7
    cvt_f32_f16<<<nW / 2048, 256>>>(Wo, wh + 3 * (size_t)nW, nW);      // 8

    hgemm_nt<1><<<gg, 512, GSMEM>>>(xh + 1 * (size_t)nX, wh + 1 * (size_t)nW, k);
    hgemm_nt<1><<<gg, 512, GSMEM>>>(xh + 2 * (size_t)nX, wh + 2 * (size_t)nW, v);

    scores_part_kernel<<<dim3(4, BH), 256>>>(q, k, key_pe, part);
    softmax64_kernel<<<(BH * DD) / 4, 128>>>(part, attn);

    av_kernel<<<dim3(NN / 64, BH), 256>>>(attn, v, ch);

    hgemm_nt<0><<<gg, 512, GSMEM>>>(ch, wh + 3 * (size_t)nW, out);
}